// round 1
// baseline (speedup 1.0000x reference)
#include <cuda_runtime.h>
#include <cuda_bf16.h>
#include <cstdint>

// ---------------- problem constants ----------------
#define NB      2
#define SEQ     2048
#define DIMM    768
#define DINNER  1536
#define DSTATE  16
#define DCONV   4
#define DTRANK  48
#define MROWS   (NB*SEQ)          // 4096
#define DBLCOLS (DTRANK + 2*DSTATE) // 80
#define VOCAB   32000
#define NCHUNK  32
#define LCHUNK  (SEQ/NCHUNK)      // 64
#define NCH     (NB*DINNER)       // 3072
#define LOG2E   1.4426950408889634f

// ---------------- device scratch ----------------
__device__ float g_x   [MROWS * DIMM];
__device__ float g_xz  [MROWS * 2 * DINNER];
__device__ float g_xssm[MROWS * DINNER];
__device__ float g_dbl [MROWS * DBLCOLS];
__device__ float g_dt  [MROWS * DINNER];
__device__ float g_y   [MROWS * DINNER];
__device__ float g_xln [MROWS * DIMM];
__device__ float g_hend  [NCHUNK * NCH * DSTATE];
__device__ float g_pend  [NCHUNK * NCH * DSTATE];
__device__ float g_hentry[NCHUNK * NCH * DSTATE];

// ---------------- SGEMM: C[M,N] = A[M,K] * B[N,K]^T (+epilogue) ----------------
// EPI 0: none. EPI 1: softplus(acc + bias[n]).
#define BM 128
#define BN 128
#define BK 16

template<int EPI>
__global__ __launch_bounds__(256) void sgemm_nt(
    int M, int N, int K,
    const float* __restrict__ A, int lda,
    const float* __restrict__ B, int ldb,
    const float* __restrict__ bias,
    float* __restrict__ C, int ldc)
{
    __shared__ float As[BK][BM];
    __shared__ float Bs[BK][BN];
    const int tid = threadIdx.x;
    const int tx = tid & 15, ty = tid >> 4;
    const int bm = blockIdx.y * BM, bn = blockIdx.x * BN;
    const int lr = tid >> 2;           // 0..63
    const int lc = (tid & 3) * 4;      // 0,4,8,12

    float acc[8][8];
    #pragma unroll
    for (int i = 0; i < 8; ++i)
        #pragma unroll
        for (int j = 0; j < 8; ++j) acc[i][j] = 0.f;

    for (int k0 = 0; k0 < K; k0 += BK) {
        #pragma unroll
        for (int p = 0; p < 2; ++p) {
            int r = lr + p * 64;
            int gm = bm + r;
            float4 v = make_float4(0.f, 0.f, 0.f, 0.f);
            if (gm < M) v = *(const float4*)(A + (size_t)gm * lda + k0 + lc);
            As[lc + 0][r] = v.x; As[lc + 1][r] = v.y;
            As[lc + 2][r] = v.z; As[lc + 3][r] = v.w;
            int gn = bn + r;
            float4 u = make_float4(0.f, 0.f, 0.f, 0.f);
            if (gn < N) u = *(const float4*)(B + (size_t)gn * ldb + k0 + lc);
            Bs[lc + 0][r] = u.x; Bs[lc + 1][r] = u.y;
            Bs[lc + 2][r] = u.z; Bs[lc + 3][r] = u.w;
        }
        __syncthreads();
        #pragma unroll
        for (int k = 0; k < BK; ++k) {
            float a[8], b[8];
            *(float4*)&a[0] = *(const float4*)&As[k][ty * 8];
            *(float4*)&a[4] = *(const float4*)&As[k][ty * 8 + 4];
            *(float4*)&b[0] = *(const float4*)&Bs[k][tx * 8];
            *(float4*)&b[4] = *(const float4*)&Bs[k][tx * 8 + 4];
            #pragma unroll
            for (int i = 0; i < 8; ++i)
                #pragma unroll
                for (int j = 0; j < 8; ++j)
                    acc[i][j] = fmaf(a[i], b[j], acc[i][j]);
        }
        __syncthreads();
    }

    #pragma unroll
    for (int i = 0; i < 8; ++i) {
        int m = bm + ty * 8 + i;
        if (m >= M) continue;
        #pragma unroll
        for (int j = 0; j < 8; ++j) {
            int n = bn + tx * 8 + j;
            if (n >= N) continue;
            float v = acc[i][j];
            if (EPI == 1) {
                v += bias[n];
                v = fmaxf(v, 0.f) + log1pf(__expf(-fabsf(v)));  // stable softplus
            }
            C[(size_t)m * ldc + n] = v;
        }
    }
}

// ---------------- embedding gather ----------------
__global__ void embed_kernel(const int* __restrict__ ids,
                             const float* __restrict__ emb,
                             float* __restrict__ out)
{
    int idx = blockIdx.x * blockDim.x + threadIdx.x;
    if (idx >= MROWS * DIMM) return;
    int row = idx / DIMM, j = idx - row * DIMM;
    out[idx] = emb[(size_t)ids[row] * DIMM + j];
}

// ---------------- depthwise causal conv (width 4) + SiLU ----------------
__global__ void conv_silu_kernel(const float* __restrict__ xz,
                                 const float* __restrict__ conv_w,
                                 const float* __restrict__ conv_b,
                                 float* __restrict__ xssm)
{
    int idx = blockIdx.x * blockDim.x + threadIdx.x;
    if (idx >= MROWS * DINNER) return;
    int d = idx % DINNER;
    int row = idx / DINNER;
    int b = row >> 11;          // /SEQ
    int t = row & (SEQ - 1);
    float acc = conv_b[d];
    #pragma unroll
    for (int k = 0; k < DCONV; ++k) {
        int tt = t + k - (DCONV - 1);
        if (tt >= 0)
            acc = fmaf(xz[((size_t)(b * SEQ + tt)) * (2 * DINNER) + d],
                       conv_w[d * DCONV + k], acc);
    }
    float s = acc / (1.f + __expf(-acc));   // silu
    xssm[idx] = s;
}

// ---------------- chunked selective scan ----------------
// dA_s(t) = exp(dt * A_s). If A_s == (s+1)*A_0 (true for this model:
// A_log = log(1..16)), use one exp2 per step and build powers by mul.
__device__ __forceinline__ void load_coef(const float* __restrict__ A_log,
                                          int d, float coef[16], bool& pw)
{
    #pragma unroll
    for (int s = 0; s < 16; ++s)
        coef[s] = -__expf(A_log[d * 16 + s]) * LOG2E;
    pw = true;
    #pragma unroll
    for (int s = 1; s < 16; ++s) {
        float r = coef[s] / coef[0];
        pw = pw && (fabsf(r - (float)(s + 1)) < 1e-3f);
    }
}

__global__ __launch_bounds__(256) void scan_phase1(
    const float* __restrict__ dtb, const float* __restrict__ xs,
    const float* __restrict__ dbl, const float* __restrict__ A_log,
    float* __restrict__ hend, float* __restrict__ pend)
{
    int id = blockIdx.x * 256 + threadIdx.x;         // NCHUNK*NCH threads
    int ch = id % NCH, c = id / NCH;
    int b = ch / DINNER, d = ch - b * DINNER;

    float coef[16]; bool pw;
    load_coef(A_log, d, coef, pw);

    float h[16], P[16];
    #pragma unroll
    for (int s = 0; s < 16; ++s) { h[s] = 0.f; P[s] = 1.f; }

    int t0 = c * LCHUNK;
    for (int t = t0; t < t0 + LCHUNK; ++t) {
        int row = b * SEQ + t;
        size_t rb = (size_t)row * DINNER + d;
        float dt = __ldg(dtb + rb), xv = __ldg(xs + rb);
        float w = dt * xv;
        const float4* Bp = (const float4*)(dbl + (size_t)row * DBLCOLS + DTRANK);
        float4 B0 = __ldg(Bp), B1 = __ldg(Bp + 1), B2 = __ldg(Bp + 2), B3 = __ldg(Bp + 3);
        float Bv[16] = {B0.x,B0.y,B0.z,B0.w, B1.x,B1.y,B1.z,B1.w,
                        B2.x,B2.y,B2.z,B2.w, B3.x,B3.y,B3.z,B3.w};
        if (pw) {
            float E = exp2f(dt * coef[0]);
            float dA = 1.f;
            #pragma unroll
            for (int s = 0; s < 16; ++s) {
                dA *= E;
                h[s] = fmaf(h[s], dA, w * Bv[s]);
                P[s] *= dA;
            }
        } else {
            #pragma unroll
            for (int s = 0; s < 16; ++s) {
                float dA = exp2f(dt * coef[s]);
                h[s] = fmaf(h[s], dA, w * Bv[s]);
                P[s] *= dA;
            }
        }
    }
    size_t off = ((size_t)c * NCH + ch) * 16;
    float4* hp = (float4*)(hend + off);
    float4* pp = (float4*)(pend + off);
    #pragma unroll
    for (int q = 0; q < 4; ++q) {
        hp[q] = make_float4(h[4*q], h[4*q+1], h[4*q+2], h[4*q+3]);
        pp[q] = make_float4(P[4*q], P[4*q+1], P[4*q+2], P[4*q+3]);
    }
}

__global__ __launch_bounds__(256) void scan_phase2(
    const float* __restrict__ hend, const float* __restrict__ pend,
    float* __restrict__ hentry)
{
    int ch = blockIdx.x * 256 + threadIdx.x;    // NCH threads
    float he[16];
    #pragma unroll
    for (int s = 0; s < 16; ++s) he[s] = 0.f;
    for (int c = 0; c < NCHUNK; ++c) {
        size_t off = ((size_t)c * NCH + ch) * 16;
        #pragma unroll
        for (int s = 0; s < 16; ++s) hentry[off + s] = he[s];
        #pragma unroll
        for (int s = 0; s < 16; ++s)
            he[s] = fmaf(pend[off + s], he[s], hend[off + s]);
    }
}

__global__ __launch_bounds__(256) void scan_phase3(
    const float* __restrict__ dtb, const float* __restrict__ xs,
    const float* __restrict__ dbl, const float* __restrict__ A_log,
    const float* __restrict__ hentry, const float* __restrict__ Dp,
    const float* __restrict__ xz, float* __restrict__ yb)
{
    int id = blockIdx.x * 256 + threadIdx.x;
    int ch = id % NCH, c = id / NCH;
    int b = ch / DINNER, d = ch - b * DINNER;

    float coef[16]; bool pw;
    load_coef(A_log, d, coef, pw);
    float Dpd = __ldg(Dp + d);

    float h[16];
    {
        size_t off = ((size_t)c * NCH + ch) * 16;
        const float4* hp = (const float4*)(hentry + off);
        #pragma unroll
        for (int q = 0; q < 4; ++q) {
            float4 v = hp[q];
            h[4*q] = v.x; h[4*q+1] = v.y; h[4*q+2] = v.z; h[4*q+3] = v.w;
        }
    }

    int t0 = c * LCHUNK;
    for (int t = t0; t < t0 + LCHUNK; ++t) {
        int row = b * SEQ + t;
        size_t rb = (size_t)row * DINNER + d;
        float dt = __ldg(dtb + rb), xv = __ldg(xs + rb);
        float w = dt * xv;
        const float4* Bp = (const float4*)(dbl + (size_t)row * DBLCOLS + DTRANK);
        const float4* Cp = (const float4*)(dbl + (size_t)row * DBLCOLS + DTRANK + DSTATE);
        float4 B0 = __ldg(Bp), B1 = __ldg(Bp + 1), B2 = __ldg(Bp + 2), B3 = __ldg(Bp + 3);
        float4 C0 = __ldg(Cp), C1 = __ldg(Cp + 1), C2 = __ldg(Cp + 2), C3 = __ldg(Cp + 3);
        float Bv[16] = {B0.x,B0.y,B0.z,B0.w, B1.x,B1.y,B1.z,B1.w,
                        B2.x,B2.y,B2.z,B2.w, B3.x,B3.y,B3.z,B3.w};
        float Cv[16] = {C0.x,C0.y,C0.z,C0.w, C1.x,C1.y,C1.z,C1.w,
                        C2.x,C2.y,C2.z,C2.w, C3.x,C3.y,C3.z,C3.w};
        float y = 0.f;
        if (pw) {
            float E = exp2f(dt * coef[0]);
            float dA = 1.f;
            #pragma unroll
            for (int s = 0; s < 16; ++s) {
                dA *= E;
                h[s] = fmaf(h[s], dA, w * Bv[s]);
                y = fmaf(h[s], Cv[s], y);
            }
        } else {
            #pragma unroll
            for (int s = 0; s < 16; ++s) {
                float dA = exp2f(dt * coef[s]);
                h[s] = fmaf(h[s], dA, w * Bv[s]);
                y = fmaf(h[s], Cv[s], y);
            }
        }
        float z = __ldg(xz + (size_t)row * (2 * DINNER) + DINNER + d);
        float yy = fmaf(xv, Dpd, y);
        float sz = z / (1.f + __expf(-z));
        yb[rb] = yy * sz;
    }
}

// ---------------- layernorm ----------------
__global__ __launch_bounds__(256) void layernorm_kernel(
    const float* __restrict__ x, const float* __restrict__ g,
    const float* __restrict__ bb, float* __restrict__ out)
{
    int row = blockIdx.x;
    const float* xr = x + (size_t)row * DIMM;
    float s = 0.f, s2 = 0.f;
    for (int j = threadIdx.x; j < DIMM; j += 256) {
        float v = xr[j];
        s += v; s2 = fmaf(v, v, s2);
    }
    #pragma unroll
    for (int o = 16; o > 0; o >>= 1) {
        s  += __shfl_xor_sync(0xffffffffu, s,  o);
        s2 += __shfl_xor_sync(0xffffffffu, s2, o);
    }
    __shared__ float rs[8], rs2[8];
    int w = threadIdx.x >> 5, l = threadIdx.x & 31;
    if (l == 0) { rs[w] = s; rs2[w] = s2; }
    __syncthreads();
    if (w == 0) {
        s  = (l < 8) ? rs[l]  : 0.f;
        s2 = (l < 8) ? rs2[l] : 0.f;
        #pragma unroll
        for (int o = 4; o > 0; o >>= 1) {
            s  += __shfl_xor_sync(0xffffffffu, s,  o);
            s2 += __shfl_xor_sync(0xffffffffu, s2, o);
        }
        if (l == 0) { rs[0] = s; rs2[0] = s2; }
    }
    __syncthreads();
    float mu = rs[0] * (1.f / DIMM);
    float var = rs2[0] * (1.f / DIMM) - mu * mu;
    float rstd = rsqrtf(var + 1e-5f);
    float* orow = out + (size_t)row * DIMM;
    for (int j = threadIdx.x; j < DIMM; j += 256)
        orow[j] = (xr[j] - mu) * rstd * g[j] + bb[j];
}

// ---------------- host launcher ----------------
extern "C" void kernel_launch(void* const* d_in, const int* in_sizes, int n_in,
                              void* d_out, int out_size)
{
    const int*   ids    = (const int*)  d_in[0];
    const float* emb    = (const float*)d_in[1];
    const float* W_in   = (const float*)d_in[2];
    const float* conv_w = (const float*)d_in[3];
    const float* conv_b = (const float*)d_in[4];
    const float* W_x    = (const float*)d_in[5];
    const float* W_dt   = (const float*)d_in[6];
    const float* b_dt   = (const float*)d_in[7];
    const float* A_log  = (const float*)d_in[8];
    const float* Dp     = (const float*)d_in[9];
    const float* W_out  = (const float*)d_in[10];
    const float* ln_g   = (const float*)d_in[11];
    const float* ln_b   = (const float*)d_in[12];
    const float* W_head = (const float*)d_in[13];
    float* logits = (float*)d_out;

    float *x, *xz, *xssm, *dbl, *dt, *y, *xln, *he, *pe, *hh;
    cudaGetSymbolAddress((void**)&x,    g_x);
    cudaGetSymbolAddress((void**)&xz,   g_xz);
    cudaGetSymbolAddress((void**)&xssm, g_xssm);
    cudaGetSymbolAddress((void**)&dbl,  g_dbl);
    cudaGetSymbolAddress((void**)&dt,   g_dt);
    cudaGetSymbolAddress((void**)&y,    g_y);
    cudaGetSymbolAddress((void**)&xln,  g_xln);
    cudaGetSymbolAddress((void**)&he,   g_hend);
    cudaGetSymbolAddress((void**)&pe,   g_pend);
    cudaGetSymbolAddress((void**)&hh,   g_hentry);

    embed_kernel<<<(MROWS * DIMM + 255) / 256, 256>>>(ids, emb, x);

    for (int i = 0; i < 4; ++i) {
        // xz = x @ W_in^T : [4096, 3072]
        sgemm_nt<0><<<dim3((2 * DINNER) / BN, MROWS / BM), 256>>>(
            MROWS, 2 * DINNER, DIMM,
            x, DIMM, W_in + (size_t)i * 2 * DINNER * DIMM, DIMM,
            nullptr, xz, 2 * DINNER);

        conv_silu_kernel<<<(MROWS * DINNER + 255) / 256, 256>>>(
            xz, conv_w + (size_t)i * DINNER * DCONV, conv_b + (size_t)i * DINNER, xssm);

        // dbl = x_ssm @ W_x^T : [4096, 80]
        sgemm_nt<0><<<dim3(1, MROWS / BM), 256>>>(
            MROWS, DBLCOLS, DINNER,
            xssm, DINNER, W_x + (size_t)i * DBLCOLS * DINNER, DINNER,
            nullptr, dbl, DBLCOLS);

        // dt = softplus(dbl[:, :48] @ W_dt^T + b_dt) : [4096, 1536]
        sgemm_nt<1><<<dim3(DINNER / BN, MROWS / BM), 256>>>(
            MROWS, DINNER, DTRANK,
            dbl, DBLCOLS, W_dt + (size_t)i * DINNER * DTRANK, DTRANK,
            b_dt + (size_t)i * DINNER, dt, DINNER);

        const float* Al = A_log + (size_t)i * DINNER * DSTATE;
        scan_phase1<<<(NCHUNK * NCH) / 256, 256>>>(dt, xssm, dbl, Al, he, pe);
        scan_phase2<<<NCH / 256, 256>>>(he, pe, hh);
        scan_phase3<<<(NCHUNK * NCH) / 256, 256>>>(dt, xssm, dbl, Al, hh,
                                                   Dp + (size_t)i * DINNER, xz, y);

        // x = y @ W_out^T : [4096, 768]
        sgemm_nt<0><<<dim3(DIMM / BN, MROWS / BM), 256>>>(
            MROWS, DIMM, DINNER,
            y, DINNER, W_out + (size_t)i * DIMM * DINNER, DINNER,
            nullptr, x, DIMM);
    }

    layernorm_kernel<<<MROWS, 256>>>(x, ln_g, ln_b, xln);

    // logits = x_ln @ W_head^T : [4096, 32000]
    sgemm_nt<0><<<dim3(VOCAB / BN, MROWS / BM), 256>>>(
        MROWS, VOCAB, DIMM,
        xln, DIMM, W_head, DIMM, nullptr, logits, VOCAB);
}

// round 2
// speedup vs baseline: 2.6641x; 2.6641x over previous
#include <cuda_runtime.h>
#include <cuda_bf16.h>
#include <cstdint>

// ---------------- problem constants ----------------
#define NB      2
#define SEQ     2048
#define DIMM    768
#define DINNER  1536
#define DSTATE  16
#define DCONV   4
#define DTRANK  48
#define MROWS   (NB*SEQ)          // 4096
#define DBLCOLS (DTRANK + 2*DSTATE) // 80
#define VOCAB   32000
#define NCHUNK  32
#define LCHUNK  (SEQ/NCHUNK)      // 64
#define NCH     (NB*DINNER)       // 3072
#define LOG2E   1.4426950408889634f

// ---------------- device scratch ----------------
__device__ float g_x   [MROWS * DIMM];
__device__ float g_xz  [MROWS * 2 * DINNER];
__device__ float g_xssm[MROWS * DINNER];
__device__ float g_dbl [MROWS * DBLCOLS];
__device__ float g_dt  [MROWS * DINNER];
__device__ float g_y   [MROWS * DINNER];
__device__ float g_xln [MROWS * DIMM];
__device__ float g_hend  [NCHUNK * NCH * DSTATE];
__device__ float g_pend  [NCHUNK * NCH * DSTATE];
__device__ float g_hentry[NCHUNK * NCH * DSTATE];

// =====================================================================
// TF32 tensor-core GEMM: C[M,N] = A[M,K] * B[N,K]^T  (+ epilogue)
// EPI 0: none. EPI 1: softplus(acc + bias[n]).
// Block tile 128x128x16, 8 warps (2x4), warp tile 64x32, mma.m16n8k8.tf32.
// Requirements: M % 128 == 0, K % 16 == 0. N arbitrary (predicated).
// =====================================================================
#define TBM 128
#define TBN 128
#define TBK 16
#define SPAD 4
#define SLD (TBK + SPAD)   // 20 floats per smem row

__device__ __forceinline__ uint32_t f2tf32(float x) {
    uint32_t r;
    asm volatile("cvt.rna.tf32.f32 %0, %1;" : "=r"(r) : "f"(x));
    return r;
}

__device__ __forceinline__ void cp_async16(void* dst_smem, const void* src_gmem, bool pred) {
    uint32_t d = (uint32_t)__cvta_generic_to_shared(dst_smem);
    int sz = pred ? 16 : 0;
    asm volatile("cp.async.ca.shared.global [%0], [%1], 16, %2;\n"
                 :: "r"(d), "l"(src_gmem), "r"(sz));
}

__device__ __forceinline__ void cp_commit() {
    asm volatile("cp.async.commit_group;\n" ::: "memory");
}
template<int N>
__device__ __forceinline__ void cp_wait() {
    asm volatile("cp.async.wait_group %0;\n" :: "n"(N) : "memory");
}

__device__ __forceinline__ void mma_tf32(float c[4], const uint32_t a[4], const uint32_t b[2]) {
    asm volatile(
        "mma.sync.aligned.m16n8k8.row.col.f32.tf32.tf32.f32 "
        "{%0,%1,%2,%3}, {%4,%5,%6,%7}, {%8,%9}, {%0,%1,%2,%3};\n"
        : "+f"(c[0]), "+f"(c[1]), "+f"(c[2]), "+f"(c[3])
        : "r"(a[0]), "r"(a[1]), "r"(a[2]), "r"(a[3]), "r"(b[0]), "r"(b[1]));
}

template<int EPI>
__global__ __launch_bounds__(256) void tf32_gemm_nt(
    int M, int N, int K,
    const float* __restrict__ A, int lda,
    const float* __restrict__ B, int ldb,
    const float* __restrict__ bias,
    float* __restrict__ C, int ldc)
{
    __shared__ float As[2][TBM][SLD];
    __shared__ float Bs[2][TBN][SLD];

    const int tid  = threadIdx.x;
    const int lane = tid & 31;
    const int warp = tid >> 5;
    const int g    = lane >> 2;     // group 0..7
    const int t4   = lane & 3;      // 0..3
    const int wm   = (warp >> 2) * 64;  // warp M offset 0/64
    const int wn   = (warp & 3) * 32;   // warp N offset 0/32/64/96

    const int bm = blockIdx.y * TBM;
    const int bn = blockIdx.x * TBN;

    // gmem->smem copy assignment: 512 chunks of 16B per tile side, 2 per thread
    // chunk c: row = c>>2, k-offset = (c&3)*4 floats
    const int r0 = tid >> 1;                  // 0..127 : covers rows via 2 chunks? no:
    // Use: c = tid + p*256 for p in {0,1}; row = c>>2, kq = (c&3)*4
    float acc[4][4][4];
    #pragma unroll
    for (int i = 0; i < 4; ++i)
        #pragma unroll
        for (int j = 0; j < 4; ++j)
            #pragma unroll
            for (int q = 0; q < 4; ++q) acc[i][j][q] = 0.f;
    (void)r0;

    const int ntiles = K / TBK;

    // prologue: load tile 0 into buffer 0
    {
        #pragma unroll
        for (int p = 0; p < 2; ++p) {
            int c = tid + p * 256;
            int row = c >> 2, kq = (c & 3) * 4;
            cp_async16(&As[0][row][kq], A + (size_t)(bm + row) * lda + kq, true);
            bool bp = (bn + row) < N;
            cp_async16(&Bs[0][row][kq],
                       B + (size_t)(bp ? (bn + row) : 0) * ldb + kq, bp);
        }
        cp_commit();
    }

    for (int tdx = 0; tdx < ntiles; ++tdx) {
        int cur = tdx & 1, nxt = cur ^ 1;
        if (tdx + 1 < ntiles) {
            int k0 = (tdx + 1) * TBK;
            #pragma unroll
            for (int p = 0; p < 2; ++p) {
                int c = tid + p * 256;
                int row = c >> 2, kq = (c & 3) * 4;
                cp_async16(&As[nxt][row][kq], A + (size_t)(bm + row) * lda + k0 + kq, true);
                bool bp = (bn + row) < N;
                cp_async16(&Bs[nxt][row][kq],
                           B + (size_t)(bp ? (bn + row) : 0) * ldb + k0 + kq, bp);
            }
        }
        cp_commit();
        cp_wait<1>();
        __syncthreads();

        #pragma unroll
        for (int ks = 0; ks < 2; ++ks) {
            const int k = ks * 8;
            uint32_t af[4][4], bf[4][2];
            #pragma unroll
            for (int mt = 0; mt < 4; ++mt) {
                int m = wm + mt * 16;
                af[mt][0] = f2tf32(As[cur][m + g     ][k + t4    ]);
                af[mt][1] = f2tf32(As[cur][m + g + 8 ][k + t4    ]);
                af[mt][2] = f2tf32(As[cur][m + g     ][k + t4 + 4]);
                af[mt][3] = f2tf32(As[cur][m + g + 8 ][k + t4 + 4]);
            }
            #pragma unroll
            for (int nt = 0; nt < 4; ++nt) {
                int n = wn + nt * 8;
                bf[nt][0] = f2tf32(Bs[cur][n + g][k + t4    ]);
                bf[nt][1] = f2tf32(Bs[cur][n + g][k + t4 + 4]);
            }
            #pragma unroll
            for (int mt = 0; mt < 4; ++mt)
                #pragma unroll
                for (int nt = 0; nt < 4; ++nt)
                    mma_tf32(acc[mt][nt], af[mt], bf[nt]);
        }
        __syncthreads();
    }

    // epilogue
    #pragma unroll
    for (int mt = 0; mt < 4; ++mt) {
        int row0 = bm + wm + mt * 16 + g;
        int row1 = row0 + 8;
        #pragma unroll
        for (int nt = 0; nt < 4; ++nt) {
            int col = bn + wn + nt * 8 + 2 * t4;
            if (col >= N) continue;
            float v0 = acc[mt][nt][0], v1 = acc[mt][nt][1];
            float v2 = acc[mt][nt][2], v3 = acc[mt][nt][3];
            if (EPI == 1) {
                float b0 = bias[col], b1 = bias[col + 1];
                v0 += b0; v1 += b1; v2 += b0; v3 += b1;
                v0 = fmaxf(v0, 0.f) + log1pf(__expf(-fabsf(v0)));
                v1 = fmaxf(v1, 0.f) + log1pf(__expf(-fabsf(v1)));
                v2 = fmaxf(v2, 0.f) + log1pf(__expf(-fabsf(v2)));
                v3 = fmaxf(v3, 0.f) + log1pf(__expf(-fabsf(v3)));
            }
            *(float2*)(C + (size_t)row0 * ldc + col) = make_float2(v0, v1);
            *(float2*)(C + (size_t)row1 * ldc + col) = make_float2(v2, v3);
        }
    }
}

// ---------------- embedding gather ----------------
__global__ void embed_kernel(const int* __restrict__ ids,
                             const float* __restrict__ emb,
                             float* __restrict__ out)
{
    int idx = blockIdx.x * blockDim.x + threadIdx.x;
    if (idx >= MROWS * DIMM) return;
    int row = idx / DIMM, j = idx - row * DIMM;
    out[idx] = emb[(size_t)ids[row] * DIMM + j];
}

// ---------------- depthwise causal conv (width 4) + SiLU ----------------
__global__ void conv_silu_kernel(const float* __restrict__ xz,
                                 const float* __restrict__ conv_w,
                                 const float* __restrict__ conv_b,
                                 float* __restrict__ xssm)
{
    int idx = blockIdx.x * blockDim.x + threadIdx.x;
    if (idx >= MROWS * DINNER) return;
    int d = idx % DINNER;
    int row = idx / DINNER;
    int b = row >> 11;          // /SEQ
    int t = row & (SEQ - 1);
    float acc = conv_b[d];
    #pragma unroll
    for (int k = 0; k < DCONV; ++k) {
        int tt = t + k - (DCONV - 1);
        if (tt >= 0)
            acc = fmaf(xz[((size_t)(b * SEQ + tt)) * (2 * DINNER) + d],
                       conv_w[d * DCONV + k], acc);
    }
    float s = acc / (1.f + __expf(-acc));   // silu
    xssm[idx] = s;
}

// ---------------- chunked selective scan ----------------
__device__ __forceinline__ void load_coef(const float* __restrict__ A_log,
                                          int d, float coef[16], bool& pw)
{
    #pragma unroll
    for (int s = 0; s < 16; ++s)
        coef[s] = -__expf(A_log[d * 16 + s]) * LOG2E;
    pw = true;
    #pragma unroll
    for (int s = 1; s < 16; ++s) {
        float r = coef[s] / coef[0];
        pw = pw && (fabsf(r - (float)(s + 1)) < 1e-3f);
    }
}

__global__ __launch_bounds__(256) void scan_phase1(
    const float* __restrict__ dtb, const float* __restrict__ xs,
    const float* __restrict__ dbl, const float* __restrict__ A_log,
    float* __restrict__ hend, float* __restrict__ pend)
{
    int id = blockIdx.x * 256 + threadIdx.x;         // NCHUNK*NCH threads
    int ch = id % NCH, c = id / NCH;
    int b = ch / DINNER, d = ch - b * DINNER;

    float coef[16]; bool pw;
    load_coef(A_log, d, coef, pw);

    float h[16], P[16];
    #pragma unroll
    for (int s = 0; s < 16; ++s) { h[s] = 0.f; P[s] = 1.f; }

    int t0 = c * LCHUNK;
    for (int t = t0; t < t0 + LCHUNK; ++t) {
        int row = b * SEQ + t;
        size_t rb = (size_t)row * DINNER + d;
        float dt = __ldg(dtb + rb), xv = __ldg(xs + rb);
        float w = dt * xv;
        const float4* Bp = (const float4*)(dbl + (size_t)row * DBLCOLS + DTRANK);
        float4 B0 = __ldg(Bp), B1 = __ldg(Bp + 1), B2 = __ldg(Bp + 2), B3 = __ldg(Bp + 3);
        float Bv[16] = {B0.x,B0.y,B0.z,B0.w, B1.x,B1.y,B1.z,B1.w,
                        B2.x,B2.y,B2.z,B2.w, B3.x,B3.y,B3.z,B3.w};
        if (pw) {
            float E = exp2f(dt * coef[0]);
            float dA = 1.f;
            #pragma unroll
            for (int s = 0; s < 16; ++s) {
                dA *= E;
                h[s] = fmaf(h[s], dA, w * Bv[s]);
                P[s] *= dA;
            }
        } else {
            #pragma unroll
            for (int s = 0; s < 16; ++s) {
                float dA = exp2f(dt * coef[s]);
                h[s] = fmaf(h[s], dA, w * Bv[s]);
                P[s] *= dA;
            }
        }
    }
    size_t off = ((size_t)c * NCH + ch) * 16;
    float4* hp = (float4*)(hend + off);
    float4* pp = (float4*)(pend + off);
    #pragma unroll
    for (int q = 0; q < 4; ++q) {
        hp[q] = make_float4(h[4*q], h[4*q+1], h[4*q+2], h[4*q+3]);
        pp[q] = make_float4(P[4*q], P[4*q+1], P[4*q+2], P[4*q+3]);
    }
}

__global__ __launch_bounds__(256) void scan_phase2(
    const float* __restrict__ hend, const float* __restrict__ pend,
    float* __restrict__ hentry)
{
    int ch = blockIdx.x * 256 + threadIdx.x;    // NCH threads
    float he[16];
    #pragma unroll
    for (int s = 0; s < 16; ++s) he[s] = 0.f;
    for (int c = 0; c < NCHUNK; ++c) {
        size_t off = ((size_t)c * NCH + ch) * 16;
        #pragma unroll
        for (int s = 0; s < 16; ++s) hentry[off + s] = he[s];
        #pragma unroll
        for (int s = 0; s < 16; ++s)
            he[s] = fmaf(pend[off + s], he[s], hend[off + s]);
    }
}

__global__ __launch_bounds__(256) void scan_phase3(
    const float* __restrict__ dtb, const float* __restrict__ xs,
    const float* __restrict__ dbl, const float* __restrict__ A_log,
    const float* __restrict__ hentry, const float* __restrict__ Dp,
    const float* __restrict__ xz, float* __restrict__ yb)
{
    int id = blockIdx.x * 256 + threadIdx.x;
    int ch = id % NCH, c = id / NCH;
    int b = ch / DINNER, d = ch - b * DINNER;

    float coef[16]; bool pw;
    load_coef(A_log, d, coef, pw);
    float Dpd = __ldg(Dp + d);

    float h[16];
    {
        size_t off = ((size_t)c * NCH + ch) * 16;
        const float4* hp = (const float4*)(hentry + off);
        #pragma unroll
        for (int q = 0; q < 4; ++q) {
            float4 v = hp[q];
            h[4*q] = v.x; h[4*q+1] = v.y; h[4*q+2] = v.z; h[4*q+3] = v.w;
        }
    }

    int t0 = c * LCHUNK;
    for (int t = t0; t < t0 + LCHUNK; ++t) {
        int row = b * SEQ + t;
        size_t rb = (size_t)row * DINNER + d;
        float dt = __ldg(dtb + rb), xv = __ldg(xs + rb);
        float w = dt * xv;
        const float4* Bp = (const float4*)(dbl + (size_t)row * DBLCOLS + DTRANK);
        const float4* Cp = (const float4*)(dbl + (size_t)row * DBLCOLS + DTRANK + DSTATE);
        float4 B0 = __ldg(Bp), B1 = __ldg(Bp + 1), B2 = __ldg(Bp + 2), B3 = __ldg(Bp + 3);
        float4 C0 = __ldg(Cp), C1 = __ldg(Cp + 1), C2 = __ldg(Cp + 2), C3 = __ldg(Cp + 3);
        float Bv[16] = {B0.x,B0.y,B0.z,B0.w, B1.x,B1.y,B1.z,B1.w,
                        B2.x,B2.y,B2.z,B2.w, B3.x,B3.y,B3.z,B3.w};
        float Cv[16] = {C0.x,C0.y,C0.z,C0.w, C1.x,C1.y,C1.z,C1.w,
                        C2.x,C2.y,C2.z,C2.w, C3.x,C3.y,C3.z,C3.w};
        float y = 0.f;
        if (pw) {
            float E = exp2f(dt * coef[0]);
            float dA = 1.f;
            #pragma unroll
            for (int s = 0; s < 16; ++s) {
                dA *= E;
                h[s] = fmaf(h[s], dA, w * Bv[s]);
                y = fmaf(h[s], Cv[s], y);
            }
        } else {
            #pragma unroll
            for (int s = 0; s < 16; ++s) {
                float dA = exp2f(dt * coef[s]);
                h[s] = fmaf(h[s], dA, w * Bv[s]);
                y = fmaf(h[s], Cv[s], y);
            }
        }
        float z = __ldg(xz + (size_t)row * (2 * DINNER) + DINNER + d);
        float yy = fmaf(xv, Dpd, y);
        float sz = z / (1.f + __expf(-z));
        yb[rb] = yy * sz;
    }
}

// ---------------- layernorm ----------------
__global__ __launch_bounds__(256) void layernorm_kernel(
    const float* __restrict__ x, const float* __restrict__ g,
    const float* __restrict__ bb, float* __restrict__ out)
{
    int row = blockIdx.x;
    const float* xr = x + (size_t)row * DIMM;
    float s = 0.f, s2 = 0.f;
    for (int j = threadIdx.x; j < DIMM; j += 256) {
        float v = xr[j];
        s += v; s2 = fmaf(v, v, s2);
    }
    #pragma unroll
    for (int o = 16; o > 0; o >>= 1) {
        s  += __shfl_xor_sync(0xffffffffu, s,  o);
        s2 += __shfl_xor_sync(0xffffffffu, s2, o);
    }
    __shared__ float rs[8], rs2[8];
    int w = threadIdx.x >> 5, l = threadIdx.x & 31;
    if (l == 0) { rs[w] = s; rs2[w] = s2; }
    __syncthreads();
    if (w == 0) {
        s  = (l < 8) ? rs[l]  : 0.f;
        s2 = (l < 8) ? rs2[l] : 0.f;
        #pragma unroll
        for (int o = 4; o > 0; o >>= 1) {
            s  += __shfl_xor_sync(0xffffffffu, s,  o);
            s2 += __shfl_xor_sync(0xffffffffu, s2, o);
        }
        if (l == 0) { rs[0] = s; rs2[0] = s2; }
    }
    __syncthreads();
    float mu = rs[0] * (1.f / DIMM);
    float var = rs2[0] * (1.f / DIMM) - mu * mu;
    float rstd = rsqrtf(var + 1e-5f);
    float* orow = out + (size_t)row * DIMM;
    for (int j = threadIdx.x; j < DIMM; j += 256)
        orow[j] = (xr[j] - mu) * rstd * g[j] + bb[j];
}

// ---------------- host launcher ----------------
extern "C" void kernel_launch(void* const* d_in, const int* in_sizes, int n_in,
                              void* d_out, int out_size)
{
    const int*   ids    = (const int*)  d_in[0];
    const float* emb    = (const float*)d_in[1];
    const float* W_in   = (const float*)d_in[2];
    const float* conv_w = (const float*)d_in[3];
    const float* conv_b = (const float*)d_in[4];
    const float* W_x    = (const float*)d_in[5];
    const float* W_dt   = (const float*)d_in[6];
    const float* b_dt   = (const float*)d_in[7];
    const float* A_log  = (const float*)d_in[8];
    const float* Dp     = (const float*)d_in[9];
    const float* W_out  = (const float*)d_in[10];
    const float* ln_g   = (const float*)d_in[11];
    const float* ln_b   = (const float*)d_in[12];
    const float* W_head = (const float*)d_in[13];
    float* logits = (float*)d_out;

    float *x, *xz, *xssm, *dbl, *dt, *y, *xln, *he, *pe, *hh;
    cudaGetSymbolAddress((void**)&x,    g_x);
    cudaGetSymbolAddress((void**)&xz,   g_xz);
    cudaGetSymbolAddress((void**)&xssm, g_xssm);
    cudaGetSymbolAddress((void**)&dbl,  g_dbl);
    cudaGetSymbolAddress((void**)&dt,   g_dt);
    cudaGetSymbolAddress((void**)&y,    g_y);
    cudaGetSymbolAddress((void**)&xln,  g_xln);
    cudaGetSymbolAddress((void**)&he,   g_hend);
    cudaGetSymbolAddress((void**)&pe,   g_pend);
    cudaGetSymbolAddress((void**)&hh,   g_hentry);

    embed_kernel<<<(MROWS * DIMM + 255) / 256, 256>>>(ids, emb, x);

    for (int i = 0; i < 4; ++i) {
        // xz = x @ W_in^T : [4096, 3072], K=768
        tf32_gemm_nt<0><<<dim3((2 * DINNER + TBN - 1) / TBN, MROWS / TBM), 256>>>(
            MROWS, 2 * DINNER, DIMM,
            x, DIMM, W_in + (size_t)i * 2 * DINNER * DIMM, DIMM,
            nullptr, xz, 2 * DINNER);

        conv_silu_kernel<<<(MROWS * DINNER + 255) / 256, 256>>>(
            xz, conv_w + (size_t)i * DINNER * DCONV, conv_b + (size_t)i * DINNER, xssm);

        // dbl = x_ssm @ W_x^T : [4096, 80], K=1536
        tf32_gemm_nt<0><<<dim3(1, MROWS / TBM), 256>>>(
            MROWS, DBLCOLS, DINNER,
            xssm, DINNER, W_x + (size_t)i * DBLCOLS * DINNER, DINNER,
            nullptr, dbl, DBLCOLS);

        // dt = softplus(dbl[:, :48] @ W_dt^T + b_dt) : [4096, 1536], K=48
        tf32_gemm_nt<1><<<dim3(DINNER / TBN, MROWS / TBM), 256>>>(
            MROWS, DINNER, DTRANK,
            dbl, DBLCOLS, W_dt + (size_t)i * DINNER * DTRANK, DTRANK,
            b_dt + (size_t)i * DINNER, dt, DINNER);

        const float* Al = A_log + (size_t)i * DINNER * DSTATE;
        scan_phase1<<<(NCHUNK * NCH) / 256, 256>>>(dt, xssm, dbl, Al, he, pe);
        scan_phase2<<<NCH / 256, 256>>>(he, pe, hh);
        scan_phase3<<<(NCHUNK * NCH) / 256, 256>>>(dt, xssm, dbl, Al, hh,
                                                   Dp + (size_t)i * DINNER, xz, y);

        // x = y @ W_out^T : [4096, 768], K=1536
        tf32_gemm_nt<0><<<dim3(DIMM / TBN, MROWS / TBM), 256>>>(
            MROWS, DIMM, DINNER,
            y, DINNER, W_out + (size_t)i * DIMM * DINNER, DINNER,
            nullptr, x, DIMM);
    }

    layernorm_kernel<<<MROWS, 256>>>(x, ln_g, ln_b, xln);

    // logits = x_ln @ W_head^T : [4096, 32000], K=768
    tf32_gemm_nt<0><<<dim3(VOCAB / TBN, MROWS / TBM), 256>>>(
        MROWS, VOCAB, DIMM,
        xln, DIMM, W_head, DIMM, nullptr, logits, VOCAB);
}